// round 1
// baseline (speedup 1.0000x reference)
#include <cuda_runtime.h>
#include <math.h>

#define L_LAYERS 250
#define N_TRACES 600
#define N_THETA  30
#define NI   (L_LAYERS - 1)            // 249 interfaces (row 249 of ref is zero -> dropped)
#define NCOL (N_TRACES * N_THETA)      // 18000
#define TOTAL (NI * NCOL)              // 4,482,000

// Scratch for rpp, layout R[k][t*N_THETA + a]  (k = interface index)
__device__ float g_R[NI * NCOL];

// ---------------------------------------------------------------------------
// Phase 1: Zoeppritz Rpp via Cramer's rule (no arcsin/sin/cos needed:
// sin(arcsin(clip(x))) = clip(x); cos(arcsin(clip(x))) = sqrt(1-clip(x)^2))
// ---------------------------------------------------------------------------
__global__ void zoe_phase1(const float* __restrict__ vp,
                           const float* __restrict__ vs,
                           const float* __restrict__ rho,
                           const float* __restrict__ theta) {
    __shared__ float s_sth[N_THETA], s_cth[N_THETA];
    int tid = threadIdx.x;
    if (tid < N_THETA) {
        float sv, cv;
        sincosf(theta[tid], &sv, &cv);
        s_sth[tid] = sv;
        s_cth[tid] = cv;
    }
    __syncthreads();

    int idx = blockIdx.x * blockDim.x + tid;
    if (idx >= TOTAL) return;

    int l = idx / NCOL;
    int n = idx - l * NCOL;
    int t = n / N_THETA;
    int a = n - t * N_THETA;

    float a1 = vp[l * N_TRACES + t],       a2 = vp[(l + 1) * N_TRACES + t];
    float b1 = vs[l * N_TRACES + t],       b2 = vs[(l + 1) * N_TRACES + t];
    float r1 = rho[l * N_TRACES + t],      r2 = rho[(l + 1) * N_TRACES + t];

    float sth = s_sth[a], cth = s_cth[a];
    float p = __fdividef(sth, a1);

    float st2 = fminf(fmaxf(p * a2, -1.f), 1.f);
    float ct2 = sqrtf(fmaxf(1.f - st2 * st2, 0.f));
    float sp1 = fminf(fmaxf(p * b1, -1.f), 1.f);
    float cp1 = sqrtf(fmaxf(1.f - sp1 * sp1, 0.f));
    float sp2 = fminf(fmaxf(p * b2, -1.f), 1.f);
    float cp2 = sqrtf(fmaxf(1.f - sp2 * sp2, 0.f));

    float rb1 = r1 * b1, rb2 = r2 * b2;
    float w1 = 1.f - 2.f * sp1 * sp1;
    float w2 = 1.f - 2.f * sp2 * sp2;

    // M matrix
    float m00 = -sth,               m01 = -cp1,                  m02 = st2,              m03 = cp2;
    float m10 =  cth,               m11 = -sp1,                  m12 = ct2,              m13 = -sp2;
    float m20 = 2.f * rb1 * sp1 * cth, m21 = rb1 * w1,           m22 = 2.f * rb2 * sp2 * ct2, m23 = rb2 * w2;
    float m30 = -r1 * a1 * w1,      m31 = 2.f * rb1 * sp1 * cp1, m32 = r2 * a2 * w2,     m33 = -2.f * rb2 * sp2 * cp2;

    // RHS (column 0 of N): n0 = -m00, n1 = m10, n2 = m20, n3 = -m30
    float n0 = sth, n1 = cth, n2 = m20, n3 = -m30;

    // Laplace on rows (0,1) x (2,3):
    float P01 = m00 * m11 - m01 * m10;
    float P02 = m00 * m12 - m02 * m10;
    float P03 = m00 * m13 - m03 * m10;
    float P12 = m01 * m12 - m02 * m11;
    float P13 = m01 * m13 - m03 * m11;
    float P23 = m02 * m13 - m03 * m12;

    float Q01 = m20 * m31 - m21 * m30;
    float Q02 = m20 * m32 - m22 * m30;
    float Q03 = m20 * m33 - m23 * m30;
    float Q12 = m21 * m32 - m22 * m31;
    float Q13 = m21 * m33 - m23 * m31;
    float Q23 = m22 * m33 - m23 * m32;

    float detM = P01 * Q23 - P02 * Q13 + P03 * Q12
               + P12 * Q03 - P13 * Q02 + P23 * Q01;

    // det of M with column 0 replaced by n: only P0j and Q0j change
    float Pn01 = n0 * m11 - m01 * n1;
    float Pn02 = n0 * m12 - m02 * n1;
    float Pn03 = n0 * m13 - m03 * n1;
    float Qn01 = n2 * m31 - m21 * n3;
    float Qn02 = n2 * m32 - m22 * n3;
    float Qn03 = n2 * m33 - m23 * n3;

    float detM0 = Pn01 * Q23 - Pn02 * Q13 + Pn03 * Q12
                + P12 * Qn03 - P13 * Qn02 + P23 * Qn01;

    g_R[l * NCOL + n] = __fdividef(detM0, detM);
}

// ---------------------------------------------------------------------------
// Phase 2: out[t, l, a] = sum_k W[l, k] * R[k, t*30+a]
// SGEMM: M=250, N=18000, K=249. BM=64, BN=128, BK=16, 256 threads, 4x8/thread
// ---------------------------------------------------------------------------
#define BM 64
#define BN 128
#define BK 16

__global__ void zoe_gemm(const float* __restrict__ W, float* __restrict__ out) {
    __shared__ float Ws[BK][BM + 4];
    __shared__ float Rs[BK][BN];

    int tid = threadIdx.x;          // 0..255
    int tr  = tid >> 4;             // 0..15 -> M groups of 4
    int tc  = tid & 15;             // 0..15 -> N groups of 8
    int bm  = blockIdx.y * BM;
    int bn  = blockIdx.x * BN;

    float acc[4][8];
#pragma unroll
    for (int i = 0; i < 4; i++)
#pragma unroll
        for (int j = 0; j < 8; j++) acc[i][j] = 0.f;

    for (int k0 = 0; k0 < NI; k0 += BK) {
        // Load W tile: BM x BK = 1024 elems, 4 per thread
#pragma unroll
        for (int i = 0; i < 4; i++) {
            int e = tid + i * 256;
            int m = e >> 4;          // 0..63
            int k = e & 15;
            int gl = bm + m, gk = k0 + k;
            float v = 0.f;
            if (gl < L_LAYERS && gk < NI) v = W[gl * L_LAYERS + gk];
            Ws[k][m] = v;
        }
        // Load R tile: BK x BN = 2048 elems = 512 float4, 2 per thread
#pragma unroll
        for (int i = 0; i < 2; i++) {
            int e  = tid + i * 256;  // float4 index in tile
            int k  = e >> 5;         // BN/4 = 32 float4 per row
            int c4 = e & 31;
            int gk = k0 + k;
            int gn = bn + c4 * 4;
            float4 v = make_float4(0.f, 0.f, 0.f, 0.f);
            if (gk < NI) {
                if (gn + 3 < NCOL) {
                    v = *(const float4*)&g_R[gk * NCOL + gn];
                } else {
                    float tmp[4] = {0.f, 0.f, 0.f, 0.f};
#pragma unroll
                    for (int j = 0; j < 4; j++)
                        if (gn + j < NCOL) tmp[j] = g_R[gk * NCOL + gn + j];
                    v = make_float4(tmp[0], tmp[1], tmp[2], tmp[3]);
                }
            }
            *(float4*)&Rs[k][c4 * 4] = v;
        }
        __syncthreads();

#pragma unroll
        for (int k = 0; k < BK; k++) {
            float4 wv = *(const float4*)&Ws[k][tr * 4];
            float4 r0 = *(const float4*)&Rs[k][tc * 8];
            float4 r1 = *(const float4*)&Rs[k][tc * 8 + 4];
            float wr[4] = {wv.x, wv.y, wv.z, wv.w};
            float rr[8] = {r0.x, r0.y, r0.z, r0.w, r1.x, r1.y, r1.z, r1.w};
#pragma unroll
            for (int i = 0; i < 4; i++)
#pragma unroll
                for (int j = 0; j < 8; j++)
                    acc[i][j] = fmaf(wr[i], rr[j], acc[i][j]);
        }
        __syncthreads();
    }

    // Write out[t*7500 + l*30 + a], n = t*30 + a
#pragma unroll
    for (int i = 0; i < 4; i++) {
        int l = bm + tr * 4 + i;
        if (l >= L_LAYERS) continue;
#pragma unroll
        for (int j = 0; j < 8; j++) {
            int n = bn + tc * 8 + j;
            if (n >= NCOL) continue;
            int t = n / N_THETA;
            int a = n - t * N_THETA;
            out[t * (L_LAYERS * N_THETA) + l * N_THETA + a] = acc[i][j];
        }
    }
}

extern "C" void kernel_launch(void* const* d_in, const int* in_sizes, int n_in,
                              void* d_out, int out_size) {
    const float* vp      = (const float*)d_in[0];
    const float* vs      = (const float*)d_in[1];
    const float* rho     = (const float*)d_in[2];
    const float* theta   = (const float*)d_in[3];
    const float* wavemat = (const float*)d_in[4];
    float* out = (float*)d_out;

    zoe_phase1<<<(TOTAL + 255) / 256, 256>>>(vp, vs, rho, theta);

    dim3 grid((NCOL + BN - 1) / BN, (L_LAYERS + BM - 1) / BM);
    zoe_gemm<<<grid, 256>>>(wavemat, out);
}